// round 11
// baseline (speedup 1.0000x reference)
#include <cuda_runtime.h>
#include <cuda_bf16.h>

// logits[i] = sum_{(i,j) in E} Wt[j] + b ; out = log_softmax(logits, axis=1)
// N=100000, E=3200000, C=64. edge_index int32 [2,E].
//
// R11 = R10 (single atomic/edge CSR, atomic-free scatter) +
//   - Wt converted to bf16 once per call -> halves the dominant 819MB gather
//     (output rel err ~1e-5, 100x under the 1e-3 gate: logits ~0.018 vs
//     output magnitude ~ln(64))
//   - zero_counts kernel dropped: scan1 re-zeroes counts after reading
//     (device statics start zeroed; every call leaves them zeroed)

#define C 64
#define MAX_N 100000       // must stay < 131072 for 17-bit row packing
#define MAX_E 3200000
#define SCAN_BLOCK 1024
#define MAX_SCAN_BLOCKS 128

__device__ int g_counts[MAX_N + 1];          // zero-init; scan1 re-zeroes each call
__device__ int g_rowptr[MAX_N + 1];
__device__ int g_blocksums[MAX_SCAN_BLOCKS];
__device__ unsigned int g_pack[MAX_E];       // (row << 15) | rank
__device__ int g_scol[MAX_E];
__device__ __nv_bfloat16 g_wbf[(size_t)MAX_N * C];   // bf16 copy of Wt

// ---------------- Wt -> bf16 ----------------

__global__ void convert_kernel(const float* __restrict__ Wt, int total4) {
    int i = blockIdx.x * blockDim.x + threadIdx.x;   // one float4 per thread
    if (i < total4) {
        float4 v = __ldg(reinterpret_cast<const float4*>(Wt) + i);
        __nv_bfloat162 h0, h1;
        h0.x = __float2bfloat16_rn(v.x);
        h0.y = __float2bfloat16_rn(v.y);
        h1.x = __float2bfloat16_rn(v.z);
        h1.y = __float2bfloat16_rn(v.w);
        uint2 pk;
        pk.x = *reinterpret_cast<unsigned*>(&h0);
        pk.y = *reinterpret_cast<unsigned*>(&h1);
        *reinterpret_cast<uint2*>(g_wbf + (size_t)i * 4) = pk;
    }
}

// ---------------- CSR build ----------------

// Histogram + per-edge rank capture (single atomic per edge)
__global__ void hist_rank_kernel(const int* __restrict__ ei, int E) {
    int i = blockIdx.x * blockDim.x + threadIdx.x;
    int e4 = i * 4;
    if (e4 + 4 <= E) {
        int4 r = __ldg(reinterpret_cast<const int4*>(ei + e4));
        int k0 = atomicAdd(&g_counts[r.x], 1);
        int k1 = atomicAdd(&g_counts[r.y], 1);
        int k2 = atomicAdd(&g_counts[r.z], 1);
        int k3 = atomicAdd(&g_counts[r.w], 1);
        uint4 p;
        p.x = ((unsigned)r.x << 15) | (unsigned)k0;
        p.y = ((unsigned)r.y << 15) | (unsigned)k1;
        p.z = ((unsigned)r.z << 15) | (unsigned)k2;
        p.w = ((unsigned)r.w << 15) | (unsigned)k3;
        *reinterpret_cast<uint4*>(g_pack + e4) = p;
    } else {
        for (int e = e4; e < E; e++) {
            int row = __ldg(&ei[e]);
            int k = atomicAdd(&g_counts[row], 1);
            g_pack[e] = ((unsigned)row << 15) | (unsigned)k;
        }
    }
}

// Per-block exclusive scan of g_counts -> g_rowptr; re-zero counts for next call
__global__ void scan1_kernel(int N) {
    __shared__ int wsum[32];
    int t = threadIdx.x;
    int i = blockIdx.x * SCAN_BLOCK + t;
    int lane = t & 31, w = t >> 5;

    int val = 0;
    if (i < N) {
        val = g_counts[i];
        g_counts[i] = 0;          // leave zeroed for the next graph replay
    }

    int x = val;
    #pragma unroll
    for (int off = 1; off < 32; off <<= 1) {
        int y = __shfl_up_sync(0xffffffffu, x, off);
        if (lane >= off) x += y;
    }
    if (lane == 31) wsum[w] = x;
    __syncthreads();

    if (w == 0) {
        int s = wsum[lane];
        #pragma unroll
        for (int off = 1; off < 32; off <<= 1) {
            int y = __shfl_up_sync(0xffffffffu, s, off);
            if (lane >= off) s += y;
        }
        wsum[lane] = s;
    }
    __syncthreads();

    int warp_excl = (w == 0) ? 0 : wsum[w - 1];
    int excl = warp_excl + x - val;
    if (i < N) g_rowptr[i] = excl;
    if (t == SCAN_BLOCK - 1) g_blocksums[blockIdx.x] = warp_excl + x;
}

// Exclusive scan of <=128 block sums: one warp, 4 elems/lane
__global__ void scan2_kernel(int nblocks) {
    int lane = threadIdx.x;
    int base = lane * 4;

    int v0 = (base + 0 < nblocks) ? g_blocksums[base + 0] : 0;
    int v1 = (base + 1 < nblocks) ? g_blocksums[base + 1] : 0;
    int v2 = (base + 2 < nblocks) ? g_blocksums[base + 2] : 0;
    int v3 = (base + 3 < nblocks) ? g_blocksums[base + 3] : 0;

    int tsum = v0 + v1 + v2 + v3;
    int x = tsum;
    #pragma unroll
    for (int off = 1; off < 32; off <<= 1) {
        int y = __shfl_up_sync(0xffffffffu, x, off);
        if (lane >= off) x += y;
    }
    int excl = x - tsum;

    if (base + 0 < nblocks) g_blocksums[base + 0] = excl;
    if (base + 1 < nblocks) g_blocksums[base + 1] = excl + v0;
    if (base + 2 < nblocks) g_blocksums[base + 2] = excl + v0 + v1;
    if (base + 3 < nblocks) g_blocksums[base + 3] = excl + v0 + v1 + v2;
}

// Add block offsets; rowptr[N] = E
__global__ void scan3_kernel(int N, int E) {
    int i = blockIdx.x * blockDim.x + threadIdx.x;
    if (i < N) {
        g_rowptr[i] += g_blocksums[i / SCAN_BLOCK];
    }
    if (i == 0) g_rowptr[N] = E;
}

// Atomic-free scatter: pos = rowptr[row] + rank
__global__ void build_scol_kernel(const int* __restrict__ ei, int E) {
    int i = blockIdx.x * blockDim.x + threadIdx.x;
    int e4 = i * 4;
    if (e4 + 4 <= E) {
        uint4 p = __ldg(reinterpret_cast<const uint4*>(g_pack + e4));
        int4  c = __ldg(reinterpret_cast<const int4*>(ei + E + e4));
        int p0 = __ldg(&g_rowptr[p.x >> 15]) + (int)(p.x & 0x7FFFu);
        int p1 = __ldg(&g_rowptr[p.y >> 15]) + (int)(p.y & 0x7FFFu);
        int p2 = __ldg(&g_rowptr[p.z >> 15]) + (int)(p.z & 0x7FFFu);
        int p3 = __ldg(&g_rowptr[p.w >> 15]) + (int)(p.w & 0x7FFFu);
        g_scol[p0] = c.x;
        g_scol[p1] = c.y;
        g_scol[p2] = c.z;
        g_scol[p3] = c.w;
    } else {
        for (int e = e4; e < E; e++) {
            unsigned p = g_pack[e];
            int col = __ldg(&ei[E + e]);
            int pos = g_rowptr[p >> 15] + (int)(p & 0x7FFFu);
            g_scol[pos] = col;
        }
    }
}

// ---------------- fused pull + bias + log_softmax (bf16 gather) ----------------

__global__ void pull_kernel(const float* __restrict__ b,
                            float* __restrict__ out,
                            int N) {
    int warp = (blockIdx.x * blockDim.x + threadIdx.x) >> 5;
    int lane = threadIdx.x & 31;
    if (warp >= N) return;

    int start = __ldg(&g_rowptr[warp]);
    int end   = __ldg(&g_rowptr[warp + 1]);

    const float2* bb = reinterpret_cast<const float2*>(b);
    float2 acc = __ldg(&bb[lane]);     // cols [2*lane, 2*lane+1]

    const unsigned* wb = reinterpret_cast<const unsigned*>(g_wbf);  // bf16x2 words

    int j = start;
    for (; j + 4 <= end; j += 4) {
        int c0 = __ldg(&g_scol[j]);
        int c1 = __ldg(&g_scol[j + 1]);
        int c2 = __ldg(&g_scol[j + 2]);
        int c3 = __ldg(&g_scol[j + 3]);
        unsigned u0 = __ldg(wb + (size_t)c0 * (C / 2) + lane);
        unsigned u1 = __ldg(wb + (size_t)c1 * (C / 2) + lane);
        unsigned u2 = __ldg(wb + (size_t)c2 * (C / 2) + lane);
        unsigned u3 = __ldg(wb + (size_t)c3 * (C / 2) + lane);
        float2 f0 = __bfloat1622float2(*reinterpret_cast<__nv_bfloat162*>(&u0));
        float2 f1 = __bfloat1622float2(*reinterpret_cast<__nv_bfloat162*>(&u1));
        float2 f2 = __bfloat1622float2(*reinterpret_cast<__nv_bfloat162*>(&u2));
        float2 f3 = __bfloat1622float2(*reinterpret_cast<__nv_bfloat162*>(&u3));
        acc.x += (f0.x + f1.x) + (f2.x + f3.x);
        acc.y += (f0.y + f1.y) + (f2.y + f3.y);
    }
    for (; j < end; j++) {
        int c = __ldg(&g_scol[j]);
        unsigned u = __ldg(wb + (size_t)c * (C / 2) + lane);
        float2 f = __bfloat1622float2(*reinterpret_cast<__nv_bfloat162*>(&u));
        acc.x += f.x;
        acc.y += f.y;
    }

    float mx = fmaxf(acc.x, acc.y);
    #pragma unroll
    for (int off = 16; off > 0; off >>= 1)
        mx = fmaxf(mx, __shfl_xor_sync(0xffffffffu, mx, off));

    float s = __expf(acc.x - mx) + __expf(acc.y - mx);
    #pragma unroll
    for (int off = 16; off > 0; off >>= 1)
        s += __shfl_xor_sync(0xffffffffu, s, off);

    float lse = mx + logf(s);
    float2 o = make_float2(acc.x - lse, acc.y - lse);
    reinterpret_cast<float2*>(out + (size_t)warp * C)[lane] = o;
}

// ---------------- fallback (push w/ atomics) for unexpected sizes ----------------

__global__ void init_kernel(float* __restrict__ out, const float* __restrict__ b, int total) {
    int i = blockIdx.x * blockDim.x + threadIdx.x;
    if (i < total) out[i] = __ldg(&b[i & (C - 1)]);
}

__global__ void scatter_kernel(const int* __restrict__ ei, const float* __restrict__ Wt,
                               float* __restrict__ out, int E) {
    int gtid = blockIdx.x * blockDim.x + threadIdx.x;
    int e = gtid >> 4;
    int lane = threadIdx.x & 15;
    if (e >= E) return;
    int row = __ldg(&ei[e]);
    int col = __ldg(&ei[E + e]);
    const float4* src = reinterpret_cast<const float4*>(Wt + (long long)col * C);
    float4 v = __ldg(&src[lane]);
    float* dst = out + (long long)row * C + lane * 4;
    asm volatile("red.global.add.v4.f32 [%0], {%1, %2, %3, %4};"
                 :: "l"(dst), "f"(v.x), "f"(v.y), "f"(v.z), "f"(v.w) : "memory");
}

__global__ void softmax_kernel(float* __restrict__ out, int N) {
    int warp = (blockIdx.x * blockDim.x + threadIdx.x) >> 5;
    int lane = threadIdx.x & 31;
    if (warp >= N) return;
    float* rowp = out + (long long)warp * C;
    float v0 = rowp[lane];
    float v1 = rowp[lane + 32];
    float m = fmaxf(v0, v1);
    #pragma unroll
    for (int off = 16; off > 0; off >>= 1)
        m = fmaxf(m, __shfl_xor_sync(0xffffffffu, m, off));
    float s = __expf(v0 - m) + __expf(v1 - m);
    #pragma unroll
    for (int off = 16; off > 0; off >>= 1)
        s += __shfl_xor_sync(0xffffffffu, s, off);
    float lse = m + logf(s);
    rowp[lane]      = v0 - lse;
    rowp[lane + 32] = v1 - lse;
}

// ---------------- launch ----------------

extern "C" void kernel_launch(void* const* d_in, const int* in_sizes, int n_in,
                              void* d_out, int out_size) {
    const int*   ei = (const int*)d_in[0];   // [2, E] int32
    const float* Wt = (const float*)d_in[1]; // [N, C]
    const float* b  = (const float*)d_in[2]; // [C]
    float* out = (float*)d_out;              // [N, C]

    int E = in_sizes[0] / 2;
    int N = in_sizes[1] / C;

    if (N <= MAX_N && E <= MAX_E && (N * C) % 4 == 0) {
        int nblocks_scan = (N + SCAN_BLOCK - 1) / SCAN_BLOCK;
        int total4 = N * C / 4;

        convert_kernel<<<(total4 + 255) / 256, 256>>>(Wt, total4);
        hist_rank_kernel<<<((E + 3) / 4 + 255) / 256, 256>>>(ei, E);
        scan1_kernel<<<nblocks_scan, SCAN_BLOCK>>>(N);
        scan2_kernel<<<1, 32>>>(nblocks_scan);
        scan3_kernel<<<(N + SCAN_BLOCK - 1) / SCAN_BLOCK, SCAN_BLOCK>>>(N, E);
        build_scol_kernel<<<((E + 3) / 4 + 255) / 256, 256>>>(ei, E);

        int threads = 256; // 8 warps per block
        int blocks = (N + 7) / 8;
        pull_kernel<<<blocks, threads>>>(b, out, N);
    } else {
        int total = N * C;
        init_kernel<<<(total + 255) / 256, 256>>>(out, b, total);
        long long work = (long long)E * 16;
        scatter_kernel<<<(int)((work + 255) / 256), 256>>>(ei, Wt, out, E);
        softmax_kernel<<<(N + 7) / 8, 256>>>(out, N);
    }
}

// round 12
// speedup vs baseline: 1.0799x; 1.0799x over previous
#include <cuda_runtime.h>
#include <cuda_bf16.h>

// logits[i] = sum_{(i,j) in E} Wt[j] + b ; out = log_softmax(logits, axis=1)
// N=100000, E=3200000, C=64. edge_index int32 [2,E].
//
// R12 = R10 CSR build (single atomic/edge, atomic-free scatter) +
//   - pull: 2 rows/warp, float4/lane (16 lanes/row). Halves warp-level LDG
//     instruction count (R11 showed pull is LDG-issue-bound, not byte-bound:
//     bf16 halved bytes, zero gain).
//   - scan2 merged into scan3 (each block sums <=98 blocksums itself).
//   - fp32 gather restored (bf16 reverted; rel_err back to ~6e-8).

#define C 64
#define MAX_N 100000       // must stay < 131072 for 17-bit row packing
#define MAX_E 3200000
#define SCAN_BLOCK 1024
#define MAX_SCAN_BLOCKS 128

__device__ int g_counts[MAX_N + 1];          // zero-init; scan1 re-zeroes each call
__device__ int g_rowptr[MAX_N + 1];
__device__ int g_blocksums[MAX_SCAN_BLOCKS];
__device__ unsigned int g_pack[MAX_E];       // (row << 15) | rank
__device__ int g_scol[MAX_E];

// ---------------- CSR build ----------------

// Histogram + per-edge rank capture (single atomic per edge)
__global__ void hist_rank_kernel(const int* __restrict__ ei, int E) {
    int i = blockIdx.x * blockDim.x + threadIdx.x;
    int e4 = i * 4;
    if (e4 + 4 <= E) {
        int4 r = __ldg(reinterpret_cast<const int4*>(ei + e4));
        int k0 = atomicAdd(&g_counts[r.x], 1);
        int k1 = atomicAdd(&g_counts[r.y], 1);
        int k2 = atomicAdd(&g_counts[r.z], 1);
        int k3 = atomicAdd(&g_counts[r.w], 1);
        uint4 p;
        p.x = ((unsigned)r.x << 15) | (unsigned)k0;
        p.y = ((unsigned)r.y << 15) | (unsigned)k1;
        p.z = ((unsigned)r.z << 15) | (unsigned)k2;
        p.w = ((unsigned)r.w << 15) | (unsigned)k3;
        *reinterpret_cast<uint4*>(g_pack + e4) = p;
    } else {
        for (int e = e4; e < E; e++) {
            int row = __ldg(&ei[e]);
            int k = atomicAdd(&g_counts[row], 1);
            g_pack[e] = ((unsigned)row << 15) | (unsigned)k;
        }
    }
}

// Per-block exclusive scan of g_counts -> g_rowptr (block-local); re-zero counts
__global__ void scan1_kernel(int N) {
    __shared__ int wsum[32];
    int t = threadIdx.x;
    int i = blockIdx.x * SCAN_BLOCK + t;
    int lane = t & 31, w = t >> 5;

    int val = 0;
    if (i < N) {
        val = g_counts[i];
        g_counts[i] = 0;          // leave zeroed for the next graph replay
    }

    int x = val;
    #pragma unroll
    for (int off = 1; off < 32; off <<= 1) {
        int y = __shfl_up_sync(0xffffffffu, x, off);
        if (lane >= off) x += y;
    }
    if (lane == 31) wsum[w] = x;
    __syncthreads();

    if (w == 0) {
        int s = wsum[lane];
        #pragma unroll
        for (int off = 1; off < 32; off <<= 1) {
            int y = __shfl_up_sync(0xffffffffu, s, off);
            if (lane >= off) s += y;
        }
        wsum[lane] = s;
    }
    __syncthreads();

    int warp_excl = (w == 0) ? 0 : wsum[w - 1];
    int excl = warp_excl + x - val;
    if (i < N) g_rowptr[i] = excl;
    if (t == SCAN_BLOCK - 1) g_blocksums[blockIdx.x] = warp_excl + x;
}

// Add block offsets (each block sums its predecessor blocksums); rowptr[N] = E
__global__ void scan3_kernel(int N, int E) {
    __shared__ int s_off;
    int t = threadIdx.x;
    if (t < 32) {
        int s = 0;
        for (int j = t; j < (int)blockIdx.x; j += 32) s += g_blocksums[j];
        #pragma unroll
        for (int off = 16; off > 0; off >>= 1)
            s += __shfl_xor_sync(0xffffffffu, s, off);
        if (t == 0) s_off = s;
    }
    __syncthreads();
    int i = blockIdx.x * SCAN_BLOCK + t;
    if (i < N) g_rowptr[i] += s_off;
    if (i == 0) g_rowptr[N] = E;
}

// Atomic-free scatter: pos = rowptr[row] + rank
__global__ void build_scol_kernel(const int* __restrict__ ei, int E) {
    int i = blockIdx.x * blockDim.x + threadIdx.x;
    int e4 = i * 4;
    if (e4 + 4 <= E) {
        uint4 p = __ldg(reinterpret_cast<const uint4*>(g_pack + e4));
        int4  c = __ldg(reinterpret_cast<const int4*>(ei + E + e4));
        int p0 = __ldg(&g_rowptr[p.x >> 15]) + (int)(p.x & 0x7FFFu);
        int p1 = __ldg(&g_rowptr[p.y >> 15]) + (int)(p.y & 0x7FFFu);
        int p2 = __ldg(&g_rowptr[p.z >> 15]) + (int)(p.z & 0x7FFFu);
        int p3 = __ldg(&g_rowptr[p.w >> 15]) + (int)(p.w & 0x7FFFu);
        g_scol[p0] = c.x;
        g_scol[p1] = c.y;
        g_scol[p2] = c.z;
        g_scol[p3] = c.w;
    } else {
        for (int e = e4; e < E; e++) {
            unsigned p = g_pack[e];
            int col = __ldg(&ei[E + e]);
            int pos = g_rowptr[p >> 15] + (int)(p & 0x7FFFu);
            g_scol[pos] = col;
        }
    }
}

// ---------------- fused pull + bias + log_softmax: 2 rows/warp ----------------

__global__ void pull_kernel(const float* __restrict__ Wt,
                            const float* __restrict__ b,
                            float* __restrict__ out,
                            int N) {
    int warp = (blockIdx.x * blockDim.x + threadIdx.x) >> 5;
    int lane = threadIdx.x & 31;
    int half = lane >> 4;          // 0 or 1
    int hl   = lane & 15;          // float4 slot within the row

    int row = warp * 2 + half;
    if (warp * 2 >= N) return;     // whole warp out of range
    bool valid = (row < N);
    int rr = valid ? row : (N - 1);   // safe index; writes guarded below

    int start = __ldg(&g_rowptr[rr]);
    int deg   = valid ? (__ldg(&g_rowptr[rr + 1]) - start) : 0;

    const float4* b4 = reinterpret_cast<const float4*>(b);
    float4 acc = __ldg(&b4[hl]);   // cols [4*hl, 4*hl+3]

    for (int base = 0; __any_sync(0xffffffffu, base < deg); base += 4) {
        if (base + 4 <= deg) {
            int c0 = __ldg(&g_scol[start + base]);
            int c1 = __ldg(&g_scol[start + base + 1]);
            int c2 = __ldg(&g_scol[start + base + 2]);
            int c3 = __ldg(&g_scol[start + base + 3]);
            float4 v0 = __ldg(reinterpret_cast<const float4*>(Wt + (size_t)c0 * C) + hl);
            float4 v1 = __ldg(reinterpret_cast<const float4*>(Wt + (size_t)c1 * C) + hl);
            float4 v2 = __ldg(reinterpret_cast<const float4*>(Wt + (size_t)c2 * C) + hl);
            float4 v3 = __ldg(reinterpret_cast<const float4*>(Wt + (size_t)c3 * C) + hl);
            acc.x += (v0.x + v1.x) + (v2.x + v3.x);
            acc.y += (v0.y + v1.y) + (v2.y + v3.y);
            acc.z += (v0.z + v1.z) + (v2.z + v3.z);
            acc.w += (v0.w + v1.w) + (v2.w + v3.w);
        } else {
            for (int k = base; k < deg; k++) {
                int c = __ldg(&g_scol[start + k]);
                float4 v = __ldg(reinterpret_cast<const float4*>(Wt + (size_t)c * C) + hl);
                acc.x += v.x; acc.y += v.y; acc.z += v.z; acc.w += v.w;
            }
        }
    }

    // log_softmax over 64 values held as 16 lanes x float4 (per half-warp)
    float mx = fmaxf(fmaxf(acc.x, acc.y), fmaxf(acc.z, acc.w));
    #pragma unroll
    for (int off = 8; off > 0; off >>= 1)
        mx = fmaxf(mx, __shfl_xor_sync(0xffffffffu, mx, off));  // stays within half

    float s = __expf(acc.x - mx) + __expf(acc.y - mx)
            + __expf(acc.z - mx) + __expf(acc.w - mx);
    #pragma unroll
    for (int off = 8; off > 0; off >>= 1)
        s += __shfl_xor_sync(0xffffffffu, s, off);

    float lse = mx + logf(s);
    if (valid) {
        float4 o = make_float4(acc.x - lse, acc.y - lse, acc.z - lse, acc.w - lse);
        reinterpret_cast<float4*>(out + (size_t)row * C)[hl] = o;
    }
}

// ---------------- fallback (push w/ atomics) for unexpected sizes ----------------

__global__ void init_kernel(float* __restrict__ out, const float* __restrict__ b, int total) {
    int i = blockIdx.x * blockDim.x + threadIdx.x;
    if (i < total) out[i] = __ldg(&b[i & (C - 1)]);
}

__global__ void scatter_kernel(const int* __restrict__ ei, const float* __restrict__ Wt,
                               float* __restrict__ out, int E) {
    int gtid = blockIdx.x * blockDim.x + threadIdx.x;
    int e = gtid >> 4;
    int lane = threadIdx.x & 15;
    if (e >= E) return;
    int row = __ldg(&ei[e]);
    int col = __ldg(&ei[E + e]);
    const float4* src = reinterpret_cast<const float4*>(Wt + (long long)col * C);
    float4 v = __ldg(&src[lane]);
    float* dst = out + (long long)row * C + lane * 4;
    asm volatile("red.global.add.v4.f32 [%0], {%1, %2, %3, %4};"
                 :: "l"(dst), "f"(v.x), "f"(v.y), "f"(v.z), "f"(v.w) : "memory");
}

__global__ void softmax_kernel(float* __restrict__ out, int N) {
    int warp = (blockIdx.x * blockDim.x + threadIdx.x) >> 5;
    int lane = threadIdx.x & 31;
    if (warp >= N) return;
    float* rowp = out + (long long)warp * C;
    float v0 = rowp[lane];
    float v1 = rowp[lane + 32];
    float m = fmaxf(v0, v1);
    #pragma unroll
    for (int off = 16; off > 0; off >>= 1)
        m = fmaxf(m, __shfl_xor_sync(0xffffffffu, m, off));
    float s = __expf(v0 - m) + __expf(v1 - m);
    #pragma unroll
    for (int off = 16; off > 0; off >>= 1)
        s += __shfl_xor_sync(0xffffffffu, s, off);
    float lse = m + logf(s);
    rowp[lane]      = v0 - lse;
    rowp[lane + 32] = v1 - lse;
}

// ---------------- launch ----------------

extern "C" void kernel_launch(void* const* d_in, const int* in_sizes, int n_in,
                              void* d_out, int out_size) {
    const int*   ei = (const int*)d_in[0];   // [2, E] int32
    const float* Wt = (const float*)d_in[1]; // [N, C]
    const float* b  = (const float*)d_in[2]; // [C]
    float* out = (float*)d_out;              // [N, C]

    int E = in_sizes[0] / 2;
    int N = in_sizes[1] / C;

    if (N <= MAX_N && E <= MAX_E) {
        int nblocks_scan = (N + SCAN_BLOCK - 1) / SCAN_BLOCK;

        hist_rank_kernel<<<((E + 3) / 4 + 255) / 256, 256>>>(ei, E);
        scan1_kernel<<<nblocks_scan, SCAN_BLOCK>>>(N);
        scan3_kernel<<<nblocks_scan, SCAN_BLOCK>>>(N, E);
        build_scol_kernel<<<((E + 3) / 4 + 255) / 256, 256>>>(ei, E);

        // 2 rows per warp, 8 warps per block -> 16 rows per block
        int blocks = (N + 15) / 16;
        pull_kernel<<<blocks, 256>>>(Wt, b, out, N);
    } else {
        int total = N * C;
        init_kernel<<<(total + 255) / 256, 256>>>(out, b, total);
        long long work = (long long)E * 16;
        scatter_kernel<<<(int)((work + 255) / 256), 256>>>(ei, Wt, out, E);
        softmax_kernel<<<(N + 7) / 8, 256>>>(out, N);
    }
}